// round 10
// baseline (speedup 1.0000x reference)
#include <cuda_runtime.h>
#include <math.h>
#include <stdint.h>

// Problem constants
#define BATCH 2
#define T 2048
#define D 1024
#define H 16
#define HD 64
#define MROWS (BATCH * T)      // 4096
#define THRESH 0.29514f
#define SHARP 15.0f
#define LN_EPS 1e-5f
#define NORM_EPS 1e-12f

// ---------------------------------------------------------------------------
// Scratch (no allocations allowed -> __device__ globals)
// ---------------------------------------------------------------------------
__device__ float g_xn[MROWS * D];     // layernorm output, row-major [4096,1024]
__device__ float g_qraw[MROWS * D];   // x_norm @ Wq, row-major
__device__ float g_kraw[MROWS * D];   // x_norm @ Wk
__device__ float g_vraw[MROWS * D];   // x @ Wv
__device__ float g_qh[MROWS * D];     // head-major [b,h,t,d], l2-normalized
__device__ float g_kh[MROWS * D];
__device__ float g_vh[MROWS * D];
__device__ float g_gq[BATCH * H * T]; // gate_q[b,h,t]
__device__ float g_gk[BATCH * H * T]; // gate_k[b,h,s]
__device__ float g_coll[MROWS * D];   // collapse, row-major [b,t,D]

// ---------------------------------------------------------------------------
// 1) LayerNorm: one block per row of 1024
// ---------------------------------------------------------------------------
__global__ __launch_bounds__(256) void ln_kernel(
    const float* __restrict__ x, const float* __restrict__ w,
    const float* __restrict__ b, float* __restrict__ out)
{
    int row = blockIdx.x;
    const float* xr = x + (size_t)row * D;
    float s = 0.f, ss = 0.f;
    float loc[4];
#pragma unroll
    for (int it = 0; it < 4; it++) {
        float v = xr[threadIdx.x + it * 256];
        loc[it] = v;
        s += v; ss += v * v;
    }
#pragma unroll
    for (int o = 16; o > 0; o >>= 1) {
        s  += __shfl_xor_sync(0xFFFFFFFFu, s,  o);
        ss += __shfl_xor_sync(0xFFFFFFFFu, ss, o);
    }
    __shared__ float red[16];
    __shared__ float mu_s, rstd_s;
    int warp = threadIdx.x >> 5, lane = threadIdx.x & 31;
    if (lane == 0) { red[warp] = s; red[warp + 8] = ss; }
    __syncthreads();
    if (threadIdx.x == 0) {
        float S = 0.f, SS = 0.f;
        for (int i = 0; i < 8; i++) { S += red[i]; SS += red[i + 8]; }
        float mu = S / D;
        float var = SS / D - mu * mu;
        mu_s = mu;
        rstd_s = rsqrtf(var + LN_EPS);
    }
    __syncthreads();
    float mu = mu_s, rstd = rstd_s;
    float* orow = out + (size_t)row * D;
#pragma unroll
    for (int it = 0; it < 4; it++) {
        int c = threadIdx.x + it * 256;
        orow[c] = (loc[it] - mu) * rstd * w[c] + b[c];
    }
}

// ---------------------------------------------------------------------------
// TF32 helpers
// ---------------------------------------------------------------------------
__device__ __forceinline__ uint32_t f2tf32(float x) {
    uint32_t r;
    asm("cvt.rna.tf32.f32 %0, %1;" : "=r"(r) : "f"(x));
    return r;
}

#define MMA_TF32(d, a0, a1, a2, a3, b0, b1)                                   \
    asm volatile(                                                             \
        "mma.sync.aligned.m16n8k8.row.col.f32.tf32.tf32.f32 "                 \
        "{%0,%1,%2,%3}, {%4,%5,%6,%7}, {%8,%9}, {%0,%1,%2,%3};"               \
        : "+f"(d[0]), "+f"(d[1]), "+f"(d[2]), "+f"(d[3])                      \
        : "r"(a0), "r"(a1), "r"(a2), "r"(a3), "r"(b0), "r"(b1))

// split x into hi=tf32(x) and lo=tf32(x - hi): ~22-bit effective mantissa
__device__ __forceinline__ void tf32_split(float x, uint32_t& hi, uint32_t& lo) {
    hi = f2tf32(x);
    lo = f2tf32(x - __uint_as_float(hi));
}

// ---------------------------------------------------------------------------
// 2) 3xTF32 tensor-core GEMM: C[M,N] = A[M,K] * B[K,N] (+bias).
//    Error-compensated: acc += Ahi*Bhi + Alo*Bhi + Ahi*Blo  (fp32-level acc).
//    128x128 block tile, BK=16 (2 k-steps of 8), 8 warps (4M x 2N),
//    warp tile 32x64 = 2 m-frags x 8 n-frags of m16n8k8.
//    Smem strides conflict-free for fragment gathers:
//      As[m][k] stride 20 -> banks 20*(lane/4)+lane%4 all distinct
//      Bs[k][n] stride 132 -> banks 4*(lane%4)+lane/4 all distinct
// ---------------------------------------------------------------------------
template <bool BIAS>
__global__ __launch_bounds__(256) void tf32x3_gemm_kernel(
    const float* __restrict__ A, const float* __restrict__ Bm,
    const float* __restrict__ bias, float* __restrict__ C,
    int M, int N, int K)
{
    __shared__ uint32_t As [128][20];
    __shared__ uint32_t dAs[128][20];
    __shared__ uint32_t Bs [16][132];
    __shared__ uint32_t dBs[16][132];

    int tid  = threadIdx.x;
    int lane = tid & 31;
    int warp = tid >> 5;
    int wm = warp & 3;     // 0..3 -> M
    int wn = warp >> 2;    // 0..1 -> N
    int lq = lane >> 2;    // lane/4 : 0..7
    int lr = lane & 3;     // lane%4 : 0..3

    int mBase = blockIdx.y << 7;
    int nBase = blockIdx.x << 7;

    // cooperative loads: A two rows (arow, arow+64) x float4; B two k-rows
    int arow = tid >> 2;           // 0..63
    int acol = (tid & 3) << 2;     // 0,4,8,12
    int brow = tid >> 5;           // 0..7
    int bcol = (tid & 31) << 2;    // 0..124

    const float* Ap0 = A + (size_t)(mBase + arow) * K + acol;
    const float* Ap1 = Ap0 + (size_t)64 * K;
    const float* Bp0 = Bm + (size_t)brow * N + nBase + bcol;
    const float* Bp1 = Bp0 + (size_t)8 * N;

    float acc[2][8][4];
#pragma unroll
    for (int mi = 0; mi < 2; mi++)
#pragma unroll
        for (int ni = 0; ni < 8; ni++)
#pragma unroll
            for (int r = 0; r < 4; r++) acc[mi][ni][r] = 0.f;

    // prefetch first tile
    float4 a0v = *(const float4*)Ap0;
    float4 a1v = *(const float4*)Ap1;
    float4 b0v = *(const float4*)Bp0;
    float4 b1v = *(const float4*)Bp1;

    for (int k0 = 0; k0 < K; k0 += 16) {
        // split + vector store to smem (hi and lo planes)
        uint4 h, l;
        tf32_split(a0v.x, h.x, l.x); tf32_split(a0v.y, h.y, l.y);
        tf32_split(a0v.z, h.z, l.z); tf32_split(a0v.w, h.w, l.w);
        *(uint4*)&As [arow][acol] = h; *(uint4*)&dAs[arow][acol] = l;
        tf32_split(a1v.x, h.x, l.x); tf32_split(a1v.y, h.y, l.y);
        tf32_split(a1v.z, h.z, l.z); tf32_split(a1v.w, h.w, l.w);
        *(uint4*)&As [arow + 64][acol] = h; *(uint4*)&dAs[arow + 64][acol] = l;
        tf32_split(b0v.x, h.x, l.x); tf32_split(b0v.y, h.y, l.y);
        tf32_split(b0v.z, h.z, l.z); tf32_split(b0v.w, h.w, l.w);
        *(uint4*)&Bs [brow][bcol] = h; *(uint4*)&dBs[brow][bcol] = l;
        tf32_split(b1v.x, h.x, l.x); tf32_split(b1v.y, h.y, l.y);
        tf32_split(b1v.z, h.z, l.z); tf32_split(b1v.w, h.w, l.w);
        *(uint4*)&Bs [brow + 8][bcol] = h; *(uint4*)&dBs[brow + 8][bcol] = l;
        __syncthreads();

        // prefetch next tile
        if (k0 + 16 < K) {
            a0v = *(const float4*)(Ap0 + k0 + 16);
            a1v = *(const float4*)(Ap1 + k0 + 16);
            b0v = *(const float4*)(Bp0 + (size_t)(k0 + 16) * N);
            b1v = *(const float4*)(Bp1 + (size_t)(k0 + 16) * N);
        }

#pragma unroll
        for (int ks = 0; ks < 16; ks += 8) {
            uint32_t af[2][4], daf[2][4];
#pragma unroll
            for (int mi = 0; mi < 2; mi++) {
                int mr = wm * 32 + mi * 16;
                af[mi][0]  = As [mr + lq][ks + lr];
                af[mi][1]  = As [mr + 8 + lq][ks + lr];
                af[mi][2]  = As [mr + lq][ks + 4 + lr];
                af[mi][3]  = As [mr + 8 + lq][ks + 4 + lr];
                daf[mi][0] = dAs[mr + lq][ks + lr];
                daf[mi][1] = dAs[mr + 8 + lq][ks + lr];
                daf[mi][2] = dAs[mr + lq][ks + 4 + lr];
                daf[mi][3] = dAs[mr + 8 + lq][ks + 4 + lr];
            }
#pragma unroll
            for (int ni = 0; ni < 8; ni++) {
                int nc = wn * 64 + ni * 8;
                uint32_t b0  = Bs [ks + lr][nc + lq];
                uint32_t b1  = Bs [ks + 4 + lr][nc + lq];
                uint32_t db0 = dBs[ks + lr][nc + lq];
                uint32_t db1 = dBs[ks + 4 + lr][nc + lq];
#pragma unroll
                for (int mi = 0; mi < 2; mi++) {
                    MMA_TF32(acc[mi][ni], daf[mi][0], daf[mi][1], daf[mi][2], daf[mi][3], b0, b1);
                    MMA_TF32(acc[mi][ni], af[mi][0],  af[mi][1],  af[mi][2],  af[mi][3],  db0, db1);
                    MMA_TF32(acc[mi][ni], af[mi][0],  af[mi][1],  af[mi][2],  af[mi][3],  b0, b1);
                }
            }
        }
        __syncthreads();
    }

    // epilogue: c0/c1 at (row, col..col+1), c2/c3 at (row+8, ...)
#pragma unroll
    for (int mi = 0; mi < 2; mi++) {
        int row = mBase + wm * 32 + mi * 16 + lq;
#pragma unroll
        for (int ni = 0; ni < 8; ni++) {
            int col = nBase + wn * 64 + ni * 8 + 2 * lr;
            float2 bb = make_float2(0.f, 0.f);
            if (BIAS) bb = *(const float2*)(bias + col);
            float2 v0 = make_float2(acc[mi][ni][0] + bb.x, acc[mi][ni][1] + bb.y);
            float2 v1 = make_float2(acc[mi][ni][2] + bb.x, acc[mi][ni][3] + bb.y);
            *(float2*)(C + (size_t)row * N + col)       = v0;
            *(float2*)(C + (size_t)(row + 8) * N + col) = v1;
        }
    }
}

// ---------------------------------------------------------------------------
// 3) Pack to head-major [b,h,t,d]; optional l2-norm + gate dot.
//    One warp per (row, head). 8 warps/block.
// ---------------------------------------------------------------------------
__global__ __launch_bounds__(256) void pack_norm_kernel(
    const float* __restrict__ raw, const float* __restrict__ gvec,
    float* __restrict__ dst, float* __restrict__ gate, int donorm)
{
    int w = blockIdx.x * 8 + (threadIdx.x >> 5);
    int lane = threadIdx.x & 31;
    int row = w >> 4;      // 0..4095
    int h = w & 15;
    int b = row >> 11;     // /T (T=2048)
    int t = row & 2047;

    const float* src = raw + (size_t)row * D + h * HD;
    float2 v = *(const float2*)(src + lane * 2);

    float scale = 1.f;
    if (donorm) {
        float ss = v.x * v.x + v.y * v.y;
#pragma unroll
        for (int o = 16; o > 0; o >>= 1)
            ss += __shfl_xor_sync(0xFFFFFFFFu, ss, o);
        float n = sqrtf(ss);
        scale = 1.f / fmaxf(n, NORM_EPS);
    }
    float2 o2;
    o2.x = v.x * scale;
    o2.y = v.y * scale;

    int bh = b * H + h;
    float* d = dst + ((size_t)bh * T + t) * HD + lane * 2;
    *(float2*)d = o2;

    if (gvec != nullptr) {
        float g = o2.x * gvec[lane * 2] + o2.y * gvec[lane * 2 + 1];
#pragma unroll
        for (int o = 16; o > 0; o >>= 1)
            g += __shfl_xor_sync(0xFFFFFFFFu, g, o);
        if (lane == 0) gate[(size_t)bh * T + t] = g;
    }
}

// ---------------------------------------------------------------------------
// 4) Attention (flash-style): block = (q-tile of 64 rows, one (b,h)).
//    Loops over s-tiles of 32: S = Q K^T, m = sigmoid((S-th)*sh)*gq*gk,
//    O += m V. Never materializes the 2048x2048 align matrix.
//    K transposed in smem (conflict-free QK); PV loop fully vectorized
//    (LDS.128 for both Ss and Vs).
// ---------------------------------------------------------------------------
__global__ __launch_bounds__(256) void attn_kernel(
    const float* __restrict__ qh, const float* __restrict__ kh,
    const float* __restrict__ vh, const float* __restrict__ gq,
    const float* __restrict__ gk, float* __restrict__ coll)
{
    __shared__ float Qs[64][68];
    __shared__ float Kt[64][34];   // transposed K tile: Kt[d][s], even stride
    __shared__ float Vs[32][68];
    __shared__ float Ss[64][36];
    __shared__ float gqs[64];
    __shared__ float gks[32];

    int bh = blockIdx.y;
    int t0 = blockIdx.x * 64;
    int tid = threadIdx.x;
    int tx = tid & 15;     // 16
    int ty = tid >> 4;     // 16

    const float* Qb = qh + ((size_t)bh * T + t0) * HD;
    // load Q tile (64x64): 1024 float4 / 256 threads = 4 each
#pragma unroll
    for (int it = 0; it < 4; it++) {
        int i = tid + it * 256;
        int r = i >> 4, c = (i & 15) << 2;
        float4 v = *(const float4*)(Qb + r * HD + c);
        Qs[r][c] = v.x; Qs[r][c + 1] = v.y; Qs[r][c + 2] = v.z; Qs[r][c + 3] = v.w;
    }
    if (tid < 64) gqs[tid] = gq[(size_t)bh * T + t0 + tid];

    float o[4][4];
#pragma unroll
    for (int i = 0; i < 4; i++)
#pragma unroll
        for (int j = 0; j < 4; j++) o[i][j] = 0.f;

    // per-thread fixed (s-row, d-col) for the K/V cooperative load
    int lr0 = tid >> 4;            // rows 0..15  (it=0)
    int lr1 = (tid + 256) >> 4;    // rows 16..31 (it=1)
    int lc = (tid & 15) << 2;

    for (int s0 = 0; s0 < T; s0 += 32) {
        const float* Kb = kh + ((size_t)bh * T + s0) * HD;
        const float* Vb = vh + ((size_t)bh * T + s0) * HD;
        // prefetch into registers (no smem touched yet)
        float4 kv0 = *(const float4*)(Kb + lr0 * HD + lc);
        float4 vv0 = *(const float4*)(Vb + lr0 * HD + lc);
        float4 kv1 = *(const float4*)(Kb + lr1 * HD + lc);
        float4 vv1 = *(const float4*)(Vb + lr1 * HD + lc);
        float gkr = (tid < 32) ? gk[(size_t)bh * T + s0 + tid] : 0.f;

        __syncthreads();   // previous-iteration readers of Kt/Vs/Ss done
        // K transposed scatter: Kt[d][s] = K[s][d]
        Kt[lc + 0][lr0] = kv0.x; Kt[lc + 1][lr0] = kv0.y;
        Kt[lc + 2][lr0] = kv0.z; Kt[lc + 3][lr0] = kv0.w;
        Kt[lc + 0][lr1] = kv1.x; Kt[lc + 1][lr1] = kv1.y;
        Kt[lc + 2][lr1] = kv1.z; Kt[lc + 3][lr1] = kv1.w;
        Vs[lr0][lc] = vv0.x; Vs[lr0][lc + 1] = vv0.y; Vs[lr0][lc + 2] = vv0.z; Vs[lr0][lc + 3] = vv0.w;
        Vs[lr1][lc] = vv1.x; Vs[lr1][lc + 1] = vv1.y; Vs[lr1][lc + 2] = vv1.z; Vs[lr1][lc + 3] = vv1.w;
        if (tid < 32) gks[tid] = gkr;
        __syncthreads();

        // S = Q K^T : thread computes 4 rows x 2 cols.
        // Q via LDS.128 (per 4 d's), K via conflict-free LDS.64.
        float acc[4][2];
#pragma unroll
        for (int i = 0; i < 4; i++) { acc[i][0] = 0.f; acc[i][1] = 0.f; }
#pragma unroll
        for (int d4 = 0; d4 < 64; d4 += 4) {
            float4 q0 = *(const float4*)&Qs[ty * 4 + 0][d4];
            float4 q1 = *(const float4*)&Qs[ty * 4 + 1][d4];
            float4 q2 = *(const float4*)&Qs[ty * 4 + 2][d4];
            float4 q3 = *(const float4*)&Qs[ty * 4 + 3][d4];
#pragma unroll
            for (int k = 0; k < 4; k++) {
                float2 kv = *(const float2*)&Kt[d4 + k][tx * 2];
                float qa = (k == 0) ? q0.x : (k == 1) ? q0.y : (k == 2) ? q0.z : q0.w;
                float qb = (k == 0) ? q1.x : (k == 1) ? q1.y : (k == 2) ? q1.z : q1.w;
                float qc = (k == 0) ? q2.x : (k == 1) ? q2.y : (k == 2) ? q2.z : q2.w;
                float qd = (k == 0) ? q3.x : (k == 1) ? q3.y : (k == 2) ? q3.z : q3.w;
                acc[0][0] += qa * kv.x; acc[0][1] += qa * kv.y;
                acc[1][0] += qb * kv.x; acc[1][1] += qb * kv.y;
                acc[2][0] += qc * kv.x; acc[2][1] += qc * kv.y;
                acc[3][0] += qd * kv.x; acc[3][1] += qd * kv.y;
            }
        }
        // modulation = sigmoid((align - th)*sh) * gq[t] * gk[s]
#pragma unroll
        for (int i = 0; i < 4; i++) {
            float gqi = gqs[ty * 4 + i];
#pragma unroll
            for (int j = 0; j < 2; j++) {
                float z = (acc[i][j] - THRESH) * SHARP;
                float m = 1.f / (1.f + __expf(-z));
                Ss[ty * 4 + i][tx * 2 + j] = m * gqi * gks[tx * 2 + j];
            }
        }
        __syncthreads();

        // O += Ss * Vs : s unrolled by 4, all smem reads LDS.128
#pragma unroll
        for (int s = 0; s < 32; s += 4) {
            float4 a0 = *(const float4*)&Ss[ty * 4 + 0][s];
            float4 a1 = *(const float4*)&Ss[ty * 4 + 1][s];
            float4 a2 = *(const float4*)&Ss[ty * 4 + 2][s];
            float4 a3 = *(const float4*)&Ss[ty * 4 + 3][s];
#pragma unroll
            for (int k = 0; k < 4; k++) {
                float4 bv = *(const float4*)&Vs[s + k][tx * 4];
                float sa = (k == 0) ? a0.x : (k == 1) ? a0.y : (k == 2) ? a0.z : a0.w;
                float sb = (k == 0) ? a1.x : (k == 1) ? a1.y : (k == 2) ? a1.z : a1.w;
                float sc = (k == 0) ? a2.x : (k == 1) ? a2.y : (k == 2) ? a2.z : a2.w;
                float sd = (k == 0) ? a3.x : (k == 1) ? a3.y : (k == 2) ? a3.z : a3.w;
                o[0][0] += sa * bv.x; o[0][1] += sa * bv.y; o[0][2] += sa * bv.z; o[0][3] += sa * bv.w;
                o[1][0] += sb * bv.x; o[1][1] += sb * bv.y; o[1][2] += sb * bv.z; o[1][3] += sb * bv.w;
                o[2][0] += sc * bv.x; o[2][1] += sc * bv.y; o[2][2] += sc * bv.z; o[2][3] += sc * bv.w;
                o[3][0] += sd * bv.x; o[3][1] += sd * bv.y; o[3][2] += sd * bv.z; o[3][3] += sd * bv.w;
            }
        }
    }

    // write collapse back in row-major [b,t,D] with head offset
    int b = bh >> 4, h = bh & 15;
#pragma unroll
    for (int i = 0; i < 4; i++) {
        int gt = t0 + ty * 4 + i;
        float* dst = coll + ((size_t)(b * T + gt)) * D + h * HD + tx * 4;
        float4 v = make_float4(o[i][0], o[i][1], o[i][2], o[i][3]);
        *(float4*)dst = v;
    }
}

// ---------------------------------------------------------------------------
// Launch
// ---------------------------------------------------------------------------
extern "C" void kernel_launch(void* const* d_in, const int* in_sizes, int n_in,
                              void* d_out, int out_size)
{
    const float* x    = (const float*)d_in[0];
    const float* Wq   = (const float*)d_in[1];
    const float* Wk   = (const float*)d_in[2];
    const float* Wv   = (const float*)d_in[3];
    const float* gq   = (const float*)d_in[4];
    const float* gk   = (const float*)d_in[5];
    const float* Wo   = (const float*)d_in[6];
    const float* bo   = (const float*)d_in[7];
    const float* ln_w = (const float*)d_in[8];
    const float* ln_b = (const float*)d_in[9];
    float* out = (float*)d_out;

    float *xn, *qraw, *kraw, *vraw, *qh, *kh, *vh, *gqv, *gkv, *coll;
    cudaGetSymbolAddress((void**)&xn,   g_xn);
    cudaGetSymbolAddress((void**)&qraw, g_qraw);
    cudaGetSymbolAddress((void**)&kraw, g_kraw);
    cudaGetSymbolAddress((void**)&vraw, g_vraw);
    cudaGetSymbolAddress((void**)&qh,   g_qh);
    cudaGetSymbolAddress((void**)&kh,   g_kh);
    cudaGetSymbolAddress((void**)&vh,   g_vh);
    cudaGetSymbolAddress((void**)&gqv,  g_gq);
    cudaGetSymbolAddress((void**)&gkv,  g_gk);
    cudaGetSymbolAddress((void**)&coll, g_coll);

    // 1) LayerNorm
    ln_kernel<<<MROWS, 256>>>(x, ln_w, ln_b, xn);

    // 2) Q/K/V projections (3xTF32 tensor cores, fp32-accurate)
    dim3 ggrid(D / 128, MROWS / 128);
    tf32x3_gemm_kernel<false><<<ggrid, 256>>>(xn, Wq, nullptr, qraw, MROWS, D, D);
    tf32x3_gemm_kernel<false><<<ggrid, 256>>>(xn, Wk, nullptr, kraw, MROWS, D, D);
    tf32x3_gemm_kernel<false><<<ggrid, 256>>>(x,  Wv, nullptr, vraw, MROWS, D, D);

    // 3) l2-normalize + gates + head-major pack
    int pack_blocks = (MROWS * H) / 8;   // 8 warps/block
    pack_norm_kernel<<<pack_blocks, 256>>>(qraw, gq, qh, gqv, 1);
    pack_norm_kernel<<<pack_blocks, 256>>>(kraw, gk, kh, gkv, 1);
    pack_norm_kernel<<<pack_blocks, 256>>>(vraw, nullptr, vh, nullptr, 0);

    // 4) fused gated attention
    dim3 agrid(T / 64, BATCH * H);
    attn_kernel<<<agrid, 256>>>(qh, kh, vh, gqv, gkv, coll);

    // 5) output projection + bias (3xTF32 tensor cores)
    tf32x3_gemm_kernel<true><<<ggrid, 256>>>(coll, Wo, bo, out, MROWS, D, D);
}

// round 11
// speedup vs baseline: 1.1900x; 1.1900x over previous
#include <cuda_runtime.h>
#include <math.h>
#include <stdint.h>

// Problem constants
#define BATCH 2
#define T 2048
#define D 1024
#define H 16
#define HD 64
#define MROWS (BATCH * T)      // 4096
#define THRESH 0.29514f
#define SHARP 15.0f
#define LN_EPS 1e-5f
#define NORM_EPS 1e-12f

// ---------------------------------------------------------------------------
// Scratch (no allocations allowed -> __device__ globals)
// ---------------------------------------------------------------------------
__device__ float g_xn[MROWS * D];     // layernorm output, row-major [4096,1024]
__device__ float g_qraw[MROWS * D];   // x_norm @ Wq, row-major
__device__ float g_kraw[MROWS * D];   // x_norm @ Wk
__device__ float g_vraw[MROWS * D];   // x @ Wv
__device__ float g_qh[MROWS * D];     // head-major [b,h,t,d], l2-normalized
__device__ float g_kh[MROWS * D];
__device__ float g_vh[MROWS * D];
__device__ float g_gq[BATCH * H * T]; // gate_q[b,h,t]
__device__ float g_gk[BATCH * H * T]; // gate_k[b,h,s]
__device__ float g_coll[MROWS * D];   // collapse, row-major [b,t,D]

// ---------------------------------------------------------------------------
// 1) LayerNorm: one block per row of 1024
// ---------------------------------------------------------------------------
__global__ __launch_bounds__(256) void ln_kernel(
    const float* __restrict__ x, const float* __restrict__ w,
    const float* __restrict__ b, float* __restrict__ out)
{
    int row = blockIdx.x;
    const float* xr = x + (size_t)row * D;
    float s = 0.f, ss = 0.f;
    float loc[4];
#pragma unroll
    for (int it = 0; it < 4; it++) {
        float v = xr[threadIdx.x + it * 256];
        loc[it] = v;
        s += v; ss += v * v;
    }
#pragma unroll
    for (int o = 16; o > 0; o >>= 1) {
        s  += __shfl_xor_sync(0xFFFFFFFFu, s,  o);
        ss += __shfl_xor_sync(0xFFFFFFFFu, ss, o);
    }
    __shared__ float red[16];
    __shared__ float mu_s, rstd_s;
    int warp = threadIdx.x >> 5, lane = threadIdx.x & 31;
    if (lane == 0) { red[warp] = s; red[warp + 8] = ss; }
    __syncthreads();
    if (threadIdx.x == 0) {
        float S = 0.f, SS = 0.f;
        for (int i = 0; i < 8; i++) { S += red[i]; SS += red[i + 8]; }
        float mu = S / D;
        float var = SS / D - mu * mu;
        mu_s = mu;
        rstd_s = rsqrtf(var + LN_EPS);
    }
    __syncthreads();
    float mu = mu_s, rstd = rstd_s;
    float* orow = out + (size_t)row * D;
#pragma unroll
    for (int it = 0; it < 4; it++) {
        int c = threadIdx.x + it * 256;
        orow[c] = (loc[it] - mu) * rstd * w[c] + b[c];
    }
}

// ---------------------------------------------------------------------------
// TF32 helpers
// ---------------------------------------------------------------------------
__device__ __forceinline__ uint32_t f2tf32(float x) {
    uint32_t r;
    asm("cvt.rna.tf32.f32 %0, %1;" : "=r"(r) : "f"(x));
    return r;
}

#define MMA_TF32(d, a0, a1, a2, a3, b0, b1)                                   \
    asm volatile(                                                             \
        "mma.sync.aligned.m16n8k8.row.col.f32.tf32.tf32.f32 "                 \
        "{%0,%1,%2,%3}, {%4,%5,%6,%7}, {%8,%9}, {%0,%1,%2,%3};"               \
        : "+f"(d[0]), "+f"(d[1]), "+f"(d[2]), "+f"(d[3])                      \
        : "r"(a0), "r"(a1), "r"(a2), "r"(a3), "r"(b0), "r"(b1))

// split x into hi=tf32(x) and lo=tf32(x - hi): ~22-bit effective mantissa
__device__ __forceinline__ void tf32_split(float x, uint32_t& hi, uint32_t& lo) {
    hi = f2tf32(x);
    lo = f2tf32(x - __uint_as_float(hi));
}

// ---------------------------------------------------------------------------
// 2) 3xTF32 tensor-core GEMM: C[M,N] = A[M,K] * B[K,N] (+bias).
//    __launch_bounds__(256,2): force <=128 regs -> 2 CTAs/SM (was reg-limited
//    to 1 CTA, occ 12.5%, issue 27.7% per R10 ncu).
// ---------------------------------------------------------------------------
template <bool BIAS>
__global__ __launch_bounds__(256, 2) void tf32x3_gemm_kernel(
    const float* __restrict__ A, const float* __restrict__ Bm,
    const float* __restrict__ bias, float* __restrict__ C,
    int M, int N, int K)
{
    __shared__ uint32_t As [128][20];
    __shared__ uint32_t dAs[128][20];
    __shared__ uint32_t Bs [16][132];
    __shared__ uint32_t dBs[16][132];

    int tid  = threadIdx.x;
    int lane = tid & 31;
    int warp = tid >> 5;
    int wm = warp & 3;     // 0..3 -> M
    int wn = warp >> 2;    // 0..1 -> N
    int lq = lane >> 2;    // lane/4 : 0..7
    int lr = lane & 3;     // lane%4 : 0..3

    int mBase = blockIdx.y << 7;
    int nBase = blockIdx.x << 7;

    int arow = tid >> 2;           // 0..63
    int acol = (tid & 3) << 2;     // 0,4,8,12
    int brow = tid >> 5;           // 0..7
    int bcol = (tid & 31) << 2;    // 0..124

    const float* Ap0 = A + (size_t)(mBase + arow) * K + acol;
    const float* Ap1 = Ap0 + (size_t)64 * K;
    const float* Bp0 = Bm + (size_t)brow * N + nBase + bcol;
    const float* Bp1 = Bp0 + (size_t)8 * N;

    float acc[2][8][4];
#pragma unroll
    for (int mi = 0; mi < 2; mi++)
#pragma unroll
        for (int ni = 0; ni < 8; ni++)
#pragma unroll
            for (int r = 0; r < 4; r++) acc[mi][ni][r] = 0.f;

    float4 a0v = *(const float4*)Ap0;
    float4 a1v = *(const float4*)Ap1;
    float4 b0v = *(const float4*)Bp0;
    float4 b1v = *(const float4*)Bp1;

    for (int k0 = 0; k0 < K; k0 += 16) {
        uint4 h, l;
        tf32_split(a0v.x, h.x, l.x); tf32_split(a0v.y, h.y, l.y);
        tf32_split(a0v.z, h.z, l.z); tf32_split(a0v.w, h.w, l.w);
        *(uint4*)&As [arow][acol] = h; *(uint4*)&dAs[arow][acol] = l;
        tf32_split(a1v.x, h.x, l.x); tf32_split(a1v.y, h.y, l.y);
        tf32_split(a1v.z, h.z, l.z); tf32_split(a1v.w, h.w, l.w);
        *(uint4*)&As [arow + 64][acol] = h; *(uint4*)&dAs[arow + 64][acol] = l;
        tf32_split(b0v.x, h.x, l.x); tf32_split(b0v.y, h.y, l.y);
        tf32_split(b0v.z, h.z, l.z); tf32_split(b0v.w, h.w, l.w);
        *(uint4*)&Bs [brow][bcol] = h; *(uint4*)&dBs[brow][bcol] = l;
        tf32_split(b1v.x, h.x, l.x); tf32_split(b1v.y, h.y, l.y);
        tf32_split(b1v.z, h.z, l.z); tf32_split(b1v.w, h.w, l.w);
        *(uint4*)&Bs [brow + 8][bcol] = h; *(uint4*)&dBs[brow + 8][bcol] = l;
        __syncthreads();

        if (k0 + 16 < K) {
            a0v = *(const float4*)(Ap0 + k0 + 16);
            a1v = *(const float4*)(Ap1 + k0 + 16);
            b0v = *(const float4*)(Bp0 + (size_t)(k0 + 16) * N);
            b1v = *(const float4*)(Bp1 + (size_t)(k0 + 16) * N);
        }

#pragma unroll
        for (int ks = 0; ks < 16; ks += 8) {
            uint32_t af[2][4], daf[2][4];
#pragma unroll
            for (int mi = 0; mi < 2; mi++) {
                int mr = wm * 32 + mi * 16;
                af[mi][0]  = As [mr + lq][ks + lr];
                af[mi][1]  = As [mr + 8 + lq][ks + lr];
                af[mi][2]  = As [mr + lq][ks + 4 + lr];
                af[mi][3]  = As [mr + 8 + lq][ks + 4 + lr];
                daf[mi][0] = dAs[mr + lq][ks + lr];
                daf[mi][1] = dAs[mr + 8 + lq][ks + lr];
                daf[mi][2] = dAs[mr + lq][ks + 4 + lr];
                daf[mi][3] = dAs[mr + 8 + lq][ks + 4 + lr];
            }
#pragma unroll
            for (int ni = 0; ni < 8; ni++) {
                int nc = wn * 64 + ni * 8;
                uint32_t b0  = Bs [ks + lr][nc + lq];
                uint32_t b1  = Bs [ks + 4 + lr][nc + lq];
                uint32_t db0 = dBs[ks + lr][nc + lq];
                uint32_t db1 = dBs[ks + 4 + lr][nc + lq];
#pragma unroll
                for (int mi = 0; mi < 2; mi++) {
                    MMA_TF32(acc[mi][ni], daf[mi][0], daf[mi][1], daf[mi][2], daf[mi][3], b0, b1);
                    MMA_TF32(acc[mi][ni], af[mi][0],  af[mi][1],  af[mi][2],  af[mi][3],  db0, db1);
                    MMA_TF32(acc[mi][ni], af[mi][0],  af[mi][1],  af[mi][2],  af[mi][3],  b0, b1);
                }
            }
        }
        __syncthreads();
    }

#pragma unroll
    for (int mi = 0; mi < 2; mi++) {
        int row = mBase + wm * 32 + mi * 16 + lq;
#pragma unroll
        for (int ni = 0; ni < 8; ni++) {
            int col = nBase + wn * 64 + ni * 8 + 2 * lr;
            float2 bb = make_float2(0.f, 0.f);
            if (BIAS) bb = *(const float2*)(bias + col);
            float2 v0 = make_float2(acc[mi][ni][0] + bb.x, acc[mi][ni][1] + bb.y);
            float2 v1 = make_float2(acc[mi][ni][2] + bb.x, acc[mi][ni][3] + bb.y);
            *(float2*)(C + (size_t)row * N + col)       = v0;
            *(float2*)(C + (size_t)(row + 8) * N + col) = v1;
        }
    }
}

// ---------------------------------------------------------------------------
// 3) Pack to head-major [b,h,t,d]; optional l2-norm + gate dot.
// ---------------------------------------------------------------------------
__global__ __launch_bounds__(256) void pack_norm_kernel(
    const float* __restrict__ raw, const float* __restrict__ gvec,
    float* __restrict__ dst, float* __restrict__ gate, int donorm)
{
    int w = blockIdx.x * 8 + (threadIdx.x >> 5);
    int lane = threadIdx.x & 31;
    int row = w >> 4;      // 0..4095
    int h = w & 15;
    int b = row >> 11;     // /T (T=2048)
    int t = row & 2047;

    const float* src = raw + (size_t)row * D + h * HD;
    float2 v = *(const float2*)(src + lane * 2);

    float scale = 1.f;
    if (donorm) {
        float ss = v.x * v.x + v.y * v.y;
#pragma unroll
        for (int o = 16; o > 0; o >>= 1)
            ss += __shfl_xor_sync(0xFFFFFFFFu, ss, o);
        float n = sqrtf(ss);
        scale = 1.f / fmaxf(n, NORM_EPS);
    }
    float2 o2;
    o2.x = v.x * scale;
    o2.y = v.y * scale;

    int bh = b * H + h;
    float* d = dst + ((size_t)bh * T + t) * HD + lane * 2;
    *(float2*)d = o2;

    if (gvec != nullptr) {
        float g = o2.x * gvec[lane * 2] + o2.y * gvec[lane * 2 + 1];
#pragma unroll
        for (int o = 16; o > 0; o >>= 1)
            g += __shfl_xor_sync(0xFFFFFFFFu, g, o);
        if (lane == 0) gate[(size_t)bh * T + t] = g;
    }
}

// ---------------------------------------------------------------------------
// 4) Tensor-core attention (3xTF32 everywhere — per R10 anchor, 1xTF32 in the
//    align path would blow the 1e-3 budget ~10x).
//    Per block: (b,h), q-tile 64. Per s-tile 32:
//      S^T[32s x 64t] = K * Q^T        (A=K row-major natural; Q transposed
//                                       ONCE per block into Qt[d][t])
//      modulation in C-fragment regs (sigmoid*gq*gk), split-stored Ss^T[s][t]
//      O[64t x 64d] += M * V           (A=M from Ss^T k-major; B=V natural)
//    All fragment gathers bank-conflict-free: banks 4lq+lr (stride 68) or
//    8lr+lq (stride 72), both lane-bijections.
//    Dynamic smem 89.4KB, 2 CTAs/SM via __launch_bounds__(256,2).
// ---------------------------------------------------------------------------
#define QT_S 72
#define K_S  68
#define V_S  72
#define SS_S 72
#define ATTN_SMEM_WORDS 22880   // = 91520 bytes

__device__ __forceinline__ float sigm15(float align) {
    float z = (align - THRESH) * SHARP;
    return 1.f / (1.f + __expf(-z));
}

__global__ __launch_bounds__(256, 2) void attn_tc_kernel(
    const float* __restrict__ qh, const float* __restrict__ kh,
    const float* __restrict__ vh, const float* __restrict__ gq,
    const float* __restrict__ gk, float* __restrict__ coll)
{
    extern __shared__ uint32_t sm[];
    uint32_t* Qthi = sm;             // [64 d][72]: Qt[d][t]
    uint32_t* Qtlo = sm + 4608;
    uint32_t* Khi  = sm + 9216;      // [32 s][68]: K[s][d]
    uint32_t* Klo  = sm + 11392;
    uint32_t* Vhi  = sm + 13568;     // [32 s][72]: V[s][d]
    uint32_t* Vlo  = sm + 15872;
    uint32_t* Shi  = sm + 18176;     // [32 s][72]: M^T[s][t]
    uint32_t* Slo  = sm + 20480;
    float* gqs = (float*)(sm + 22784);   // 64
    float* gks = (float*)(sm + 22848);   // 32

    int bh = blockIdx.y;
    int t0 = blockIdx.x * 64;
    int tid = threadIdx.x;
    int lane = tid & 31, warp = tid >> 5;
    int lq = lane >> 2, lr = lane & 3;
    int wmS = warp & 1, wnS = warp >> 1;   // QK: 2M(s) x 4N(t), warp tile 16x16
    int wmO = warp & 3, wnO = warp >> 2;   // PV: 4M(t) x 2N(d), warp tile 16x32

    // ---- Q: load + transpose + split, once per block ----
    const float* Qb = qh + ((size_t)bh * T + t0) * HD;
#pragma unroll
    for (int it = 0; it < 4; it++) {
        int i = tid + it * 256;
        int r = i >> 4, c = (i & 15) << 2;    // r = t row, c = d col
        float4 qv = *(const float4*)(Qb + r * HD + c);
        uint32_t h_, l_;
        tf32_split(qv.x, h_, l_); Qthi[(c + 0) * QT_S + r] = h_; Qtlo[(c + 0) * QT_S + r] = l_;
        tf32_split(qv.y, h_, l_); Qthi[(c + 1) * QT_S + r] = h_; Qtlo[(c + 1) * QT_S + r] = l_;
        tf32_split(qv.z, h_, l_); Qthi[(c + 2) * QT_S + r] = h_; Qtlo[(c + 2) * QT_S + r] = l_;
        tf32_split(qv.w, h_, l_); Qthi[(c + 3) * QT_S + r] = h_; Qtlo[(c + 3) * QT_S + r] = l_;
    }
    if (tid < 64) gqs[tid] = gq[(size_t)bh * T + t0 + tid];

    float accO[4][4];
#pragma unroll
    for (int ni = 0; ni < 4; ni++)
#pragma unroll
        for (int r = 0; r < 4; r++) accO[ni][r] = 0.f;

    int kr = tid >> 3;            // 0..31  (s row)
    int kc = (tid & 7) << 3;      // 0,8,..,56 (d col, 8 each)

    for (int s0 = 0; s0 < T; s0 += 32) {
        // prefetch K, V into regs before the barrier
        const float* Kb = kh + ((size_t)bh * T + s0) * HD;
        const float* Vb = vh + ((size_t)bh * T + s0) * HD;
        float4 kva = *(const float4*)(Kb + kr * HD + kc);
        float4 kvb = *(const float4*)(Kb + kr * HD + kc + 4);
        float4 vva = *(const float4*)(Vb + kr * HD + kc);
        float4 vvb = *(const float4*)(Vb + kr * HD + kc + 4);
        float gkr = (tid < 32) ? gk[(size_t)bh * T + s0 + tid] : 0.f;

        __syncthreads();   // prev iter's PV (reads V,Ss) and QK (reads K) done
        {
            uint32_t h_, l_;
            tf32_split(kva.x, h_, l_); Khi[kr * K_S + kc + 0] = h_; Klo[kr * K_S + kc + 0] = l_;
            tf32_split(kva.y, h_, l_); Khi[kr * K_S + kc + 1] = h_; Klo[kr * K_S + kc + 1] = l_;
            tf32_split(kva.z, h_, l_); Khi[kr * K_S + kc + 2] = h_; Klo[kr * K_S + kc + 2] = l_;
            tf32_split(kva.w, h_, l_); Khi[kr * K_S + kc + 3] = h_; Klo[kr * K_S + kc + 3] = l_;
            tf32_split(kvb.x, h_, l_); Khi[kr * K_S + kc + 4] = h_; Klo[kr * K_S + kc + 4] = l_;
            tf32_split(kvb.y, h_, l_); Khi[kr * K_S + kc + 5] = h_; Klo[kr * K_S + kc + 5] = l_;
            tf32_split(kvb.z, h_, l_); Khi[kr * K_S + kc + 6] = h_; Klo[kr * K_S + kc + 6] = l_;
            tf32_split(kvb.w, h_, l_); Khi[kr * K_S + kc + 7] = h_; Klo[kr * K_S + kc + 7] = l_;
            tf32_split(vva.x, h_, l_); Vhi[kr * V_S + kc + 0] = h_; Vlo[kr * V_S + kc + 0] = l_;
            tf32_split(vva.y, h_, l_); Vhi[kr * V_S + kc + 1] = h_; Vlo[kr * V_S + kc + 1] = l_;
            tf32_split(vva.z, h_, l_); Vhi[kr * V_S + kc + 2] = h_; Vlo[kr * V_S + kc + 2] = l_;
            tf32_split(vva.w, h_, l_); Vhi[kr * V_S + kc + 3] = h_; Vlo[kr * V_S + kc + 3] = l_;
            tf32_split(vvb.x, h_, l_); Vhi[kr * V_S + kc + 4] = h_; Vlo[kr * V_S + kc + 4] = l_;
            tf32_split(vvb.y, h_, l_); Vhi[kr * V_S + kc + 5] = h_; Vlo[kr * V_S + kc + 5] = l_;
            tf32_split(vvb.z, h_, l_); Vhi[kr * V_S + kc + 6] = h_; Vlo[kr * V_S + kc + 6] = l_;
            tf32_split(vvb.w, h_, l_); Vhi[kr * V_S + kc + 7] = h_; Vlo[kr * V_S + kc + 7] = l_;
        }
        if (tid < 32) gks[tid] = gkr;
        __syncthreads();

        // ---- QK: S^T[s][t] = K * Q^T, 3xTF32 ----
        float accS[2][4];
#pragma unroll
        for (int ni = 0; ni < 2; ni++)
#pragma unroll
            for (int r = 0; r < 4; r++) accS[ni][r] = 0.f;
        int mrS = wmS * 16;
#pragma unroll
        for (int kk = 0; kk < 8; kk++) {
            int ks = kk * 8;
            uint32_t ah0 = Khi[(mrS + lq) * K_S + ks + lr];
            uint32_t ah1 = Khi[(mrS + 8 + lq) * K_S + ks + lr];
            uint32_t ah2 = Khi[(mrS + lq) * K_S + ks + 4 + lr];
            uint32_t ah3 = Khi[(mrS + 8 + lq) * K_S + ks + 4 + lr];
            uint32_t al0 = Klo[(mrS + lq) * K_S + ks + lr];
            uint32_t al1 = Klo[(mrS + 8 + lq) * K_S + ks + lr];
            uint32_t al2 = Klo[(mrS + lq) * K_S + ks + 4 + lr];
            uint32_t al3 = Klo[(mrS + 8 + lq) * K_S + ks + 4 + lr];
#pragma unroll
            for (int ni = 0; ni < 2; ni++) {
                int nc = wnS * 16 + ni * 8;
                uint32_t qb0 = Qthi[(ks + lr) * QT_S + nc + lq];
                uint32_t qb1 = Qthi[(ks + 4 + lr) * QT_S + nc + lq];
                uint32_t ql0 = Qtlo[(ks + lr) * QT_S + nc + lq];
                uint32_t ql1 = Qtlo[(ks + 4 + lr) * QT_S + nc + lq];
                MMA_TF32(accS[ni], al0, al1, al2, al3, qb0, qb1);   // Klo*Qhi
                MMA_TF32(accS[ni], ah0, ah1, ah2, ah3, ql0, ql1);   // Khi*Qlo
                MMA_TF32(accS[ni], ah0, ah1, ah2, ah3, qb0, qb1);   // Khi*Qhi
            }
        }
        // ---- sigmoid * gq[t] * gk[s] in fragment regs, split-store M^T ----
        int sA = mrS + lq, sB = sA + 8;
        float gkA = gks[sA], gkB = gks[sB];
#pragma unroll
        for (int ni = 0; ni < 2; ni++) {
            int tC = wnS * 16 + ni * 8 + 2 * lr;
            float gq0 = gqs[tC], gq1 = gqs[tC + 1];
            float m0 = sigm15(accS[ni][0]) * gq0 * gkA;
            float m1 = sigm15(accS[ni][1]) * gq1 * gkA;
            float m2 = sigm15(accS[ni][2]) * gq0 * gkB;
            float m3 = sigm15(accS[ni][3]) * gq1 * gkB;
            uint32_t h_, l_;
            tf32_split(m0, h_, l_); Shi[sA * SS_S + tC]     = h_; Slo[sA * SS_S + tC]     = l_;
            tf32_split(m1, h_, l_); Shi[sA * SS_S + tC + 1] = h_; Slo[sA * SS_S + tC + 1] = l_;
            tf32_split(m2, h_, l_); Shi[sB * SS_S + tC]     = h_; Slo[sB * SS_S + tC]     = l_;
            tf32_split(m3, h_, l_); Shi[sB * SS_S + tC + 1] = h_; Slo[sB * SS_S + tC + 1] = l_;
        }
        __syncthreads();

        // ---- PV: O[t][d] += M * V, 3xTF32 ----
        int mrO = wmO * 16;
#pragma unroll
        for (int kk = 0; kk < 4; kk++) {
            int ks = kk * 8;
            uint32_t ah0 = Shi[(ks + lr) * SS_S + mrO + lq];
            uint32_t ah1 = Shi[(ks + lr) * SS_S + mrO + 8 + lq];
            uint32_t ah2 = Shi[(ks + 4 + lr) * SS_S + mrO + lq];
            uint32_t ah3 = Shi[(ks + 4 + lr) * SS_S + mrO + 8 + lq];
            uint32_t al0 = Slo[(ks + lr) * SS_S + mrO + lq];
            uint32_t al1 = Slo[(ks + lr) * SS_S + mrO + 8 + lq];
            uint32_t al2 = Slo[(ks + 4 + lr) * SS_S + mrO + lq];
            uint32_t al3 = Slo[(ks + 4 + lr) * SS_S + mrO + 8 + lq];
#pragma unroll
            for (int ni = 0; ni < 4; ni++) {
                int nc = wnO * 32 + ni * 8;
                uint32_t vb0 = Vhi[(ks + lr) * V_S + nc + lq];
                uint32_t vb1 = Vhi[(ks + 4 + lr) * V_S + nc + lq];
                uint32_t vl0 = Vlo[(ks + lr) * V_S + nc + lq];
                uint32_t vl1 = Vlo[(ks + 4 + lr) * V_S + nc + lq];
                MMA_TF32(accO[ni], al0, al1, al2, al3, vb0, vb1);   // Mlo*Vhi
                MMA_TF32(accO[ni], ah0, ah1, ah2, ah3, vl0, vl1);   // Mhi*Vlo
                MMA_TF32(accO[ni], ah0, ah1, ah2, ah3, vb0, vb1);   // Mhi*Vhi
            }
        }
    }

    // ---- epilogue: O fragments -> coll[b, t, D] ----
    int b = bh >> 4, h = bh & 15;
    int tR = wmO * 16 + lq;
#pragma unroll
    for (int ni = 0; ni < 4; ni++) {
        int d = wnO * 32 + ni * 8 + 2 * lr;
        float* dst0 = coll + ((size_t)(b * T + t0 + tR)) * D + h * HD + d;
        float* dst1 = coll + ((size_t)(b * T + t0 + tR + 8)) * D + h * HD + d;
        *(float2*)dst0 = make_float2(accO[ni][0], accO[ni][1]);
        *(float2*)dst1 = make_float2(accO[ni][2], accO[ni][3]);
    }
}

// ---------------------------------------------------------------------------
// Launch
// ---------------------------------------------------------------------------
extern "C" void kernel_launch(void* const* d_in, const int* in_sizes, int n_in,
                              void* d_out, int out_size)
{
    const float* x    = (const float*)d_in[0];
    const float* Wq   = (const float*)d_in[1];
    const float* Wk   = (const float*)d_in[2];
    const float* Wv   = (const float*)d_in[3];
    const float* gq   = (const float*)d_in[4];
    const float* gk   = (const float*)d_in[5];
    const float* Wo   = (const float*)d_in[6];
    const float* bo   = (const float*)d_in[7];
    const float* ln_w = (const float*)d_in[8];
    const float* ln_b = (const float*)d_in[9];
    float* out = (float*)d_out;

    float *xn, *qraw, *kraw, *vraw, *qh, *kh, *vh, *gqv, *gkv, *coll;
    cudaGetSymbolAddress((void**)&xn,   g_xn);
    cudaGetSymbolAddress((void**)&qraw, g_qraw);
    cudaGetSymbolAddress((void**)&kraw, g_kraw);
    cudaGetSymbolAddress((void**)&vraw, g_vraw);
    cudaGetSymbolAddress((void**)&qh,   g_qh);
    cudaGetSymbolAddress((void**)&kh,   g_kh);
    cudaGetSymbolAddress((void**)&vh,   g_vh);
    cudaGetSymbolAddress((void**)&gqv,  g_gq);
    cudaGetSymbolAddress((void**)&gkv,  g_gk);
    cudaGetSymbolAddress((void**)&coll, g_coll);

    // opt into >48KB dynamic smem for the attention kernel (idempotent)
    cudaFuncSetAttribute((const void*)attn_tc_kernel,
                         cudaFuncAttributeMaxDynamicSharedMemorySize,
                         ATTN_SMEM_WORDS * 4);

    // 1) LayerNorm
    ln_kernel<<<MROWS, 256>>>(x, ln_w, ln_b, xn);

    // 2) Q/K/V projections (3xTF32 tensor cores)
    dim3 ggrid(D / 128, MROWS / 128);
    tf32x3_gemm_kernel<false><<<ggrid, 256>>>(xn, Wq, nullptr, qraw, MROWS, D, D);
    tf32x3_gemm_kernel<false><<<ggrid, 256>>>(xn, Wk, nullptr, kraw, MROWS, D, D);
    tf32x3_gemm_kernel<false><<<ggrid, 256>>>(x,  Wv, nullptr, vraw, MROWS, D, D);

    // 3) l2-normalize + gates + head-major pack
    int pack_blocks = (MROWS * H) / 8;
    pack_norm_kernel<<<pack_blocks, 256>>>(qraw, gq, qh, gqv, 1);
    pack_norm_kernel<<<pack_blocks, 256>>>(kraw, gk, kh, gkv, 1);
    pack_norm_kernel<<<pack_blocks, 256>>>(vraw, nullptr, vh, nullptr, 0);

    // 4) fused gated attention (3xTF32 tensor cores)
    dim3 agrid(T / 64, BATCH * H);
    attn_tc_kernel<<<agrid, 256, ATTN_SMEM_WORDS * 4>>>(qh, kh, vh, gqv, gkv, coll);

    // 5) output projection + bias (3xTF32 tensor cores)
    tf32x3_gemm_kernel<true><<<ggrid, 256>>>(coll, Wo, bo, out, MROWS, D, D);
}